// round 17
// baseline (speedup 1.0000x reference)
#include <cuda_runtime.h>
#include <math_constants.h>

typedef unsigned int u32;

// img (1,200,200,512) f32 NHWC, rois (1,128,4) f32 (x,y,w,h), pool 7x7
// out (1,128,7,7,512) f32.
#define IMG_H 200
#define IMG_W 200
#define IMG_C 512
#define C4    128               // float4 per full pixel record
#define POOLP 7
#define NROIS 128
#define NBINS 49
#define NBIN_TOT (NROIS * NBINS)   // 6272

#define TW 20
#define TH 20
#define NTX (IMG_W / TW)        // 10
#define NTY (IMG_H / TH)        // 10
#define NTILES (NTX * NTY)      // 100

#define NCHUNK 4                // channel chunks per tile (128 ch each)
#define CH4    32               // float4 per chunk per pixel
#define SLAB   (TH * TW * CH4)  // 12800 float4 = 204.8 KB

#define LCAP   448              // SMEM worklist entries (avg ~63 owned bins/tile)
#define OCAP   (NBIN_TOT - LCAP)

// ---- device scratch (static: allocation-free) ----------------------------
// Private per-CTA worklist overflow (worst case: all bins owned by one tile).
__device__ uint2 g_ovf[NTILES * NCHUNK][OCAP];   // 18.6 MB

// Exact JAX f32 boundary: step = w/7; b[k] = int(x + k*step); mul->add, no fma.
__device__ __forceinline__ int bin_edge(float base, float step, int k) {
    return (int)__fadd_rn(base, __fmul_rn((float)k, step));
}

#define FMAX4(M, V) \
    M.x = fmaxf(M.x, V.x); M.y = fmaxf(M.y, V.y); \
    M.z = fmaxf(M.z, V.z); M.w = fmaxf(M.w, V.w);

// ---- single fused kernel -------------------------------------------------
// CTA = (20x20 tile, 128-channel chunk), 512 threads, 204.8 KB slab.
// Each bin is computed ENTIRELY by the CTA owning its top-left pixel:
// in-tile pixels from SMEM (conflict-free 512 B LDS.128/warp, lane=channel),
// out-of-tile pixels straight from L2 (coalesced 512 B LDG/warp).
// Every output written exactly once -> no partials, no reduce kernel.
__global__ __launch_bounds__(512, 1) void roi_kernel(const float4* __restrict__ img4,
                                                     const float* __restrict__ rois,
                                                     float4* __restrict__ out4)
{
    extern __shared__ float4 smem[];
    float4* tilebuf = smem;                       // SLAB float4
    uint2*  s_list  = (uint2*)(smem + SLAB);      // LCAP entries

    __shared__ short s_bx[NROIS][8];
    __shared__ short s_by[NROIS][8];
    __shared__ unsigned char s_hit[NROIS];
    __shared__ int s_nhit, s_cnt, s_next;

    const int tid   = threadIdx.x;
    const int chunk = blockIdx.x & (NCHUNK - 1);
    const int tile  = blockIdx.x >> 2;
    const int tx = tile % NTX, ty = tile / NTX;
    const int x0 = tx * TW,    y0 = ty * TH;
    const int co = chunk * CH4 + (tid & 31);      // lane's channel float4 slot

    if (tid == 0) { s_nhit = 0; s_cnt = 0; s_next = 0; }
    __syncthreads();

    // -- phase A (threads 0..127): exact ROI bin edges + owner-bbox test ---
    if (tid < NROIS) {
        const int r = tid;
        float rx = __ldg(&rois[r * 4 + 0]), ry = __ldg(&rois[r * 4 + 1]);
        float rw = __ldg(&rois[r * 4 + 2]), rh = __ldg(&rois[r * 4 + 3]);
        float sx = __fdiv_rn(rw, 7.0f);
        float sy = __fdiv_rn(rh, 7.0f);
        int b0x = 0, b6x = 0, b0y = 0, b6y = 0;
        #pragma unroll
        for (int k = 0; k < 8; k++) {
            int vx = bin_edge(rx, sx, k);
            int vy = bin_edge(ry, sy, k);
            s_bx[r][k] = (short)vx;
            s_by[r][k] = (short)vy;
            if (k == 0) { b0x = vx; b0y = vy; }
            if (k == 6) { b6x = vx; b6y = vy; }
        }
        // some bin top-left (bx[0..6], by[0..6]) could lie in this tile?
        if (b0x < x0 + TW && b6x >= x0 && b0y < y0 + TH && b6y >= y0) {
            int idx = atomicAdd(&s_nhit, 1);
            s_hit[idx] = (unsigned char)r;
        }
    }

    // -- stage slab (all threads; overlaps phase-A latency) ----------------
    {
        const float4* __restrict__ src = img4 + chunk * CH4;
        #pragma unroll 5
        for (int i = tid; i < SLAB; i += 512) {
            int p = i >> 5;                       // pixel 0..399
            int c = i & 31;
            int py = p / TW;
            int px = p - py * TW;
            tilebuf[i] = src[((y0 + py) * IMG_W + (x0 + px)) * C4 + c];
        }
    }
    __syncthreads();

    // -- phase B: emit owned bins (top-left pixel inside this tile) --------
    const int units = s_nhit * NBINS;
    for (int u = tid; u < units; u += 512) {
        int r   = s_hit[u / NBINS];
        int bin = u % NBINS;
        int jy  = bin / POOLP;
        int ix  = bin - jy * POOLP;
        int bx0 = s_bx[r][ix], bx1 = s_bx[r][ix + 1];
        int by0 = s_by[r][jy], by1 = s_by[r][jy + 1];
        if (bx0 >= x0 && bx0 < x0 + TW && by0 >= y0 && by0 < y0 + TH) {
            uint2 en = make_uint2(
                (u32)bx0 | ((u32)bx1 << 8) | ((u32)by0 << 16) | ((u32)by1 << 24),
                (u32)(r * NBINS + bin));
            int idx = atomicAdd(&s_cnt, 1);
            if (idx < LCAP) s_list[idx] = en;
            else            g_ovf[blockIdx.x][idx - LCAP] = en;
        }
    }
    __syncthreads();
    const int n = s_cnt;

    // -- sweep: dynamic warp ticket over owned bins ------------------------
    const int lane = tid & 31;

    for (;;) {
        int e;
        if (lane == 0) e = atomicAdd(&s_next, 1);
        e = __shfl_sync(0xffffffffu, e, 0);
        if (e >= n) break;

        uint2 en = (e < LCAP) ? s_list[e] : g_ovf[blockIdx.x][e - LCAP];
        int bx0 = en.x & 255, bx1 = (en.x >> 8) & 255;
        int by0 = (en.x >> 16) & 255, by1 = en.x >> 24;

        float4 m0 = make_float4(-CUDART_INF_F, -CUDART_INF_F,
                                -CUDART_INF_F, -CUDART_INF_F);
        float4 m1 = m0;

        for (int y = by0; y < by1; y++) {
            // home segment [hs, he) of this row lives in the slab
            int hs = max(bx0, x0), he = min(bx1, x0 + TW);
            if ((u32)(y - y0) >= TH || hs > he) { hs = bx1; he = bx1; }

            const float4* __restrict__ gp =
                img4 + ((size_t)y * IMG_W) * C4 + co;

            // remote-left [bx0, hs) via L2
            {
                int x = bx0;
                for (; x + 1 < hs; x += 2) {
                    float4 v0 = __ldg(&gp[(size_t)x * C4]);
                    float4 v1 = __ldg(&gp[(size_t)(x + 1) * C4]);
                    FMAX4(m0, v0); FMAX4(m1, v1);
                }
                if (x < hs) { float4 v0 = __ldg(&gp[(size_t)x * C4]); FMAX4(m0, v0); }
            }
            // home [hs, he) via SMEM
            {
                const float4* rp = tilebuf + ((y - y0) * TW + (hs - x0)) * CH4 + lane;
                int nx = he - hs;
                int x = 0;
                for (; x + 1 < nx; x += 2) {
                    float4 v0 = rp[x * CH4];
                    float4 v1 = rp[(x + 1) * CH4];
                    FMAX4(m0, v0); FMAX4(m1, v1);
                }
                if (x < nx) { float4 v0 = rp[x * CH4]; FMAX4(m0, v0); }
            }
            // remote-right [he, bx1) via L2
            {
                int x = he;
                for (; x + 1 < bx1; x += 2) {
                    float4 v0 = __ldg(&gp[(size_t)x * C4]);
                    float4 v1 = __ldg(&gp[(size_t)(x + 1) * C4]);
                    FMAX4(m0, v0); FMAX4(m1, v1);
                }
                if (x < bx1) { float4 v0 = __ldg(&gp[(size_t)x * C4]); FMAX4(m0, v0); }
            }
        }
        FMAX4(m0, m1);

        out4[(size_t)en.y * C4 + co] = m0;        // 512 B coalesced, written once
    }
}

// ---- launch --------------------------------------------------------------
extern "C" void kernel_launch(void* const* d_in, const int* in_sizes, int n_in,
                              void* d_out, int out_size)
{
    const float* img  = (const float*)d_in[0];
    const float* rois = (const float*)d_in[1];
    float4* out = (float4*)d_out;

    const int smem_bytes = SLAB * (int)sizeof(float4)        // 204800
                         + LCAP * (int)sizeof(uint2);        // 3584
    cudaFuncSetAttribute(roi_kernel,
                         cudaFuncAttributeMaxDynamicSharedMemorySize, smem_bytes);

    roi_kernel<<<NTILES * NCHUNK, 512, smem_bytes>>>((const float4*)img, rois, out);
}